// round 12
// baseline (speedup 1.0000x reference)
#include <cuda_runtime.h>
#include <cuda_fp16.h>
#include <cstdint>
#include <math.h>

#define BB   64
#define NN   4096
#define DD   64
#define HH   256
#define SS   1024
#define TOT  49152   // 3 * D * H
#define WPB  24576   // half2 words per batch (3*D*H/2)
#define K1_TILES 384

// raw hypernet output (k1 -> k2)
__device__ float g_params[BB * (size_t)TOT];
// normalized fp16 weights, half2-packed along k, XOR-swizzled (k2 -> k3)
__device__ uint32_t g_wT[BB * (size_t)WPB];
// work queue for persistent k1
__device__ unsigned int g_tile_ctr;

// ======================= helpers =======================
__device__ __forceinline__ float tanha(float x) {
    float y;
    asm("tanh.approx.f32 %0, %1;" : "=f"(y) : "f"(x));
    return y;
}
__device__ __forceinline__ uint32_t pack2(float lo, float hi) {
    __half2 h = __floats2half2_rn(lo, hi);
    return *(uint32_t*)&h;
}
__device__ __forceinline__ uint32_t smem_u32(const void* p) {
    uint32_t a;
    asm("{ .reg .u64 t; cvta.to.shared.u64 t, %1; cvt.u32.u64 %0, t; }" : "=r"(a) : "l"(p));
    return a;
}
__device__ __forceinline__ void cpa16(uint32_t dst, const void* src) {
    asm volatile("cp.async.cg.shared.global [%0], [%1], 16;" :: "r"(dst), "l"(src));
}
#define CP_COMMIT() asm volatile("cp.async.commit_group;" ::: "memory")
#define CP_WAIT0()  asm volatile("cp.async.wait_group 0;" ::: "memory")
#define CP_WAIT1()  asm volatile("cp.async.wait_group 1;" ::: "memory")

// D += A * B  (m16n8k8, tf32 inputs, fp32 accum) — kernel 1
__device__ __forceinline__ void mma_tf32(float* d, const uint32_t* a, uint32_t b0, uint32_t b1) {
    asm volatile("mma.sync.aligned.m16n8k8.row.col.f32.tf32.tf32.f32 "
                 "{%0,%1,%2,%3}, {%4,%5,%6,%7}, {%8,%9}, {%0,%1,%2,%3};"
                 : "+f"(d[0]), "+f"(d[1]), "+f"(d[2]), "+f"(d[3])
                 : "r"(a[0]), "r"(a[1]), "r"(a[2]), "r"(a[3]), "r"(b0), "r"(b1));
}
// D += A * B  (m16n8k16, fp16 inputs, fp32 accum) — kernel 3
__device__ __forceinline__ void mma_f16(float* d, const uint32_t* a, uint32_t b0, uint32_t b1) {
    asm volatile("mma.sync.aligned.m16n8k16.row.col.f32.f16.f16.f32 "
                 "{%0,%1,%2,%3}, {%4,%5,%6,%7}, {%8,%9}, {%0,%1,%2,%3};"
                 : "+f"(d[0]), "+f"(d[1]), "+f"(d[2]), "+f"(d[3])
                 : "r"(a[0]), "r"(a[1]), "r"(a[2]), "r"(a[3]), "r"(b0), "r"(b1));
}

// ======================= kernel 1: persistent tf32 GEMM with atomic tile queue =======================
__global__ void k1_reset() { g_tile_ctr = 0u; }

#define K1_SMEM ((2 * 64 * 36 + 2 * 32 * 136) * 4)   // 53248 B

__global__ __launch_bounds__(256) void k1_mma(const float* __restrict__ s,
                                              const float* __restrict__ W,
                                              const float* __restrict__ bias) {
    extern __shared__ float sk[];
    float* sA = sk;              // 2 * 2304
    float* sB = sk + 4608;       // 2 * 4352
    __shared__ int s_tile;
    const int tid = threadIdx.x;
    const int w = tid >> 5, lane = tid & 31;
    const int r = lane >> 2, q = lane & 3;
    const int m0 = (w & 1) * 32, nw = (w >> 1) * 32;
    const uint32_t sbA = smem_u32(sA), sbB = smem_u32(sB);

    #define K1_LOAD(st, k0, n0) do {                                               \
        _Pragma("unroll")                                                          \
        for (int i = 0; i < 2; i++) {                                              \
            int c = tid + i * 256;                                                 \
            int row = c >> 3, cc = c & 7;                                          \
            cpa16(sbA + (uint32_t)((st) * 2304 + row * 36 + cc * 4) * 4,           \
                  s + (size_t)row * SS + (k0) + cc * 4);                           \
        }                                                                          \
        _Pragma("unroll")                                                          \
        for (int i = 0; i < 4; i++) {                                              \
            int c = tid + i * 256;                                                 \
            int row = c >> 5, cc = c & 31;                                         \
            cpa16(sbB + (uint32_t)((st) * 4352 + row * 136 + cc * 4) * 4,          \
                  W + (size_t)((k0) + row) * TOT + (n0) + cc * 4);                 \
        }                                                                          \
    } while (0)

    for (;;) {
        __syncthreads();   // prior tile's smem reads + s_tile reads done
        if (tid == 0) s_tile = (int)atomicAdd(&g_tile_ctr, 1u);
        __syncthreads();
        const int t = s_tile;
        if (t >= K1_TILES) break;
        const int n0 = t * 128;

        float acc[2][4][4];
        #pragma unroll
        for (int mf = 0; mf < 2; mf++)
            #pragma unroll
            for (int nf = 0; nf < 4; nf++)
                acc[mf][nf][0] = acc[mf][nf][1] = acc[mf][nf][2] = acc[mf][nf][3] = 0.f;

        K1_LOAD(0, 0, n0);  CP_COMMIT();
        K1_LOAD(1, 32, n0); CP_COMMIT();

        for (int ks = 0; ks < 32; ks++) {
            CP_WAIT1();
            __syncthreads();
            const int st = ks & 1;
            const float* A  = sA + st * 2304;
            const float* Bp = sB + st * 4352;
            #pragma unroll
            for (int kk = 0; kk < 4; kk++) {
                uint32_t a[2][4];
                #pragma unroll
                for (int mf = 0; mf < 2; mf++) {
                    const int mr = m0 + mf * 16 + r;
                    a[mf][0] = __float_as_uint(A[mr * 36 + kk * 8 + q]);
                    a[mf][1] = __float_as_uint(A[(mr + 8) * 36 + kk * 8 + q]);
                    a[mf][2] = __float_as_uint(A[mr * 36 + kk * 8 + q + 4]);
                    a[mf][3] = __float_as_uint(A[(mr + 8) * 36 + kk * 8 + q + 4]);
                }
                #pragma unroll
                for (int nf = 0; nf < 4; nf++) {
                    const int cb = nw + nf * 8 + r;
                    uint32_t b0 = __float_as_uint(Bp[(kk * 8 + q) * 136 + cb]);
                    uint32_t b1 = __float_as_uint(Bp[(kk * 8 + q + 4) * 136 + cb]);
                    mma_tf32(acc[0][nf], a[0], b0, b1);
                    mma_tf32(acc[1][nf], a[1], b0, b1);
                }
            }
            __syncthreads();
            const int kn = (ks + 2) * 32;
            if (kn < SS) { K1_LOAD(st, kn, n0); }
            CP_COMMIT();
        }
        CP_WAIT0();   // drain before next tile overwrites stages

        #pragma unroll
        for (int nf = 0; nf < 4; nf++) {
            float2 bv = *(const float2*)(bias + n0 + nw + nf * 8 + 2 * q);
            #pragma unroll
            for (int mf = 0; mf < 2; mf++) {
                const int mr = m0 + mf * 16 + r;
                float* o0 = g_params + (size_t)mr * TOT + n0 + nw + nf * 8 + 2 * q;
                *(float2*)o0 = make_float2(acc[mf][nf][0] + bv.x, acc[mf][nf][1] + bv.y);
                float* o1 = g_params + (size_t)(mr + 8) * TOT + n0 + nw + nf * 8 + 2 * q;
                *(float2*)o1 = make_float2(acc[mf][nf][2] + bv.x, acc[mf][nf][3] + bv.y);
            }
        }
    }
    #undef K1_LOAD
}

// ======================= kernel 2: normalize -> fp16 swizzled, grid (64, 4) =======================
// quadrant owns Wg/Wv h-cols [64q, 64q+64) and fc2 d-cols [16q, 16q+16)
__global__ __launch_bounds__(256) void k2_normalize() {
    __shared__ float red[256];
    __shared__ float sinv[64];
    const int b = blockIdx.x, quad = blockIdx.y, tid = threadIdx.x;
    const float* P = g_params + (size_t)b * TOT;
    uint32_t* dst = g_wT + (size_t)b * WPB;

    // ---- Wg, Wv: norm over d per column h ----
    #pragma unroll
    for (int m = 0; m < 2; m++) {
        const float* src = P + m * 16384;
        const int hl = tid & 63, part = tid >> 6;
        const int h = quad * 64 + hl;
        {
            float ss = 0.f;
            #pragma unroll 4
            for (int d = part * 16; d < part * 16 + 16; d++) {
                float v = src[d * 256 + h];
                ss += v * v;
            }
            red[tid] = ss;
        }
        __syncthreads();
        if (tid < 64)
            sinv[tid] = 1.f / fmaxf(sqrtf(red[tid] + red[tid + 64] + red[tid + 128] + red[tid + 192]), 1e-12f);
        __syncthreads();
        #pragma unroll
        for (int i = 0; i < 8; i++) {
            int idx = tid + i * 256;                 // 2048 words
            int kp = idx >> 6, hl2 = idx & 63;
            int h2 = quad * 64 + hl2;
            float inv = sinv[hl2];
            float a = src[(2 * kp) * 256 + h2] * inv;
            float c = src[(2 * kp + 1) * 256 + h2] * inv;
            dst[m * 8192 + kp * 256 + (h2 ^ ((kp & 3) << 3))] = pack2(a, c);
        }
        __syncthreads();
    }
    // ---- fc2: norm over h per column d ----
    {
        const float* src = P + 32768;
        const int dl = tid & 15, part = tid >> 4;
        const int d = quad * 16 + dl;
        {
            float ss = 0.f;
            #pragma unroll 4
            for (int h = part * 16; h < part * 16 + 16; h++) {
                float v = src[h * 64 + d];
                ss += v * v;
            }
            red[tid] = ss;
        }
        __syncthreads();
        if (tid < 16) {
            float t = 0.f;
            #pragma unroll
            for (int p = 0; p < 16; p++) t += red[p * 16 + tid];
            sinv[tid] = 1.f / fmaxf(sqrtf(t), 1e-12f);
        }
        __syncthreads();
        #pragma unroll
        for (int i = 0; i < 8; i++) {
            int idx = tid + i * 256;                 // 2048 words
            int hp = idx >> 4, dl2 = idx & 15;
            int d2 = quad * 16 + dl2;
            float inv = sinv[dl2];
            float a = src[(2 * hp) * 64 + d2] * inv;
            float c = src[(2 * hp + 1) * 64 + d2] * inv;
            dst[16384 + hp * 64 + (d2 ^ ((hp & 3) << 3))] = pack2(a, c);
        }
    }
}

// ======================= kernel 3: fp16 mma, warp = 32-row m-pair x full H (frozen R11 winner) =======================
#define K3_XN_OFF 24640
#define K3_SMEM   ((24576 + 64 + 9216) * 4)   // 135424 B

__global__ __launch_bounds__(256, 1) void k3_main(const float* __restrict__ x,
                                                  const float* __restrict__ scale,
                                                  float* __restrict__ out) {
    extern __shared__ uint32_t su[];
    float* ssc = (float*)(su + 24576);       // scale [64]
    uint32_t* xnw = su + K3_XN_OFF;          // [256][36] half2 words
    const int tid = threadIdx.x, w = tid >> 5, lane = tid & 31;
    const int b = blockIdx.x >> 4;
    const int row0 = (blockIdx.x & 15) * 256;
    const int m0 = w * 32;
    const int r = lane >> 2, q = lane & 3, q8 = q << 3;
    const uint32_t sb = smem_u32(su);

    {
        const uint32_t* wsrc = g_wT + (size_t)b * WPB;
        #pragma unroll 6
        for (int i = tid; i < 6144; i += 256)
            cpa16(sb + (uint32_t)i * 16, wsrc + i * 4);
        CP_COMMIT();
    }
    if (tid < 64) ssc[tid] = scale[tid];
    __syncthreads();

    {
        const float4* xr = (const float4*)(x + ((size_t)b * NN + row0 + tid) * DD);
        float4 v[16];
        float ssq = 0.f;
        #pragma unroll
        for (int i = 0; i < 16; i++) {
            v[i] = xr[i];
            ssq += v[i].x * v[i].x + v[i].y * v[i].y + v[i].z * v[i].z + v[i].w * v[i].w;
        }
        const float rr = rsqrtf(ssq * (1.0f / 64.0f) + 1e-6f);
        uint32_t* xd = xnw + tid * 36;
        #pragma unroll
        for (int i = 0; i < 8; i++) {
            float4 a = v[2 * i], c = v[2 * i + 1];
            float4 sA = *(const float4*)&ssc[8 * i];
            float4 sB = *(const float4*)&ssc[8 * i + 4];
            uint4 o;
            o.x = pack2(a.x * rr * sA.x, a.y * rr * sA.y);
            o.y = pack2(a.z * rr * sA.z, a.w * rr * sA.w);
            o.z = pack2(c.x * rr * sB.x, c.y * rr * sB.y);
            o.w = pack2(c.z * rr * sB.z, c.w * rr * sB.w);
            *(uint4*)&xd[4 * i] = o;
        }
    }
    CP_WAIT0();
    __syncthreads();

    const uint32_t* Wg = su;
    const uint32_t* Wv = su + 8192;
    const uint32_t* Wf = su + 16384;

    uint32_t xa[4][2][4];
    #pragma unroll
    for (int kt = 0; kt < 4; kt++) {
        #pragma unroll
        for (int mf = 0; mf < 2; mf++) {
            const uint32_t* xb = xnw + (m0 + mf * 16 + r) * 36 + kt * 8 + q;
            xa[kt][mf][0] = xb[0];
            xa[kt][mf][1] = xb[8 * 36];
            xa[kt][mf][2] = xb[4];
            xa[kt][mf][3] = xb[8 * 36 + 4];
        }
    }

    float oacc[2][8][4];
    #pragma unroll
    for (int mf = 0; mf < 2; mf++)
        #pragma unroll
        for (int i = 0; i < 8; i++)
            oacc[mf][i][0] = oacc[mf][i][1] = oacc[mf][i][2] = oacc[mf][i][3] = 0.f;

    #pragma unroll 4
    for (int ch = 0; ch < 16; ch++) {
        const int nc = ch * 16;
        float ga[2][2][4], va[2][2][4];
        #pragma unroll
        for (int mf = 0; mf < 2; mf++)
            #pragma unroll
            for (int nt = 0; nt < 2; nt++) {
                ga[mf][nt][0] = ga[mf][nt][1] = ga[mf][nt][2] = ga[mf][nt][3] = 0.f;
                va[mf][nt][0] = va[mf][nt][1] = va[mf][nt][2] = va[mf][nt][3] = 0.f;
            }
        const int c0 = (nc ^ q8) + r;
        const int c1 = ((nc + 8) ^ q8) + r;
        #pragma unroll
        for (int kt = 0; kt < 4; kt++) {
            const uint32_t* g0 = Wg + (kt * 8 + q) * 256;
            const uint32_t* g1 = Wg + (kt * 8 + q + 4) * 256;
            const uint32_t* v0 = Wv + (kt * 8 + q) * 256;
            const uint32_t* v1 = Wv + (kt * 8 + q + 4) * 256;
            uint32_t gb00 = g0[c0], gb10 = g1[c0], gb01 = g0[c1], gb11 = g1[c1];
            uint32_t vb00 = v0[c0], vb10 = v1[c0], vb01 = v0[c1], vb11 = v1[c1];
            #pragma unroll
            for (int mf = 0; mf < 2; mf++) {
                mma_f16(ga[mf][0], xa[kt][mf], gb00, gb10);
                mma_f16(ga[mf][1], xa[kt][mf], gb01, gb11);
                mma_f16(va[mf][0], xa[kt][mf], vb00, vb10);
                mma_f16(va[mf][1], xa[kt][mf], vb01, vb11);
            }
        }

        const int hp0 = ch * 8;
        const uint32_t* f0 = Wf + (hp0 + q) * 64;
        const uint32_t* f1 = Wf + (hp0 + q + 4) * 64;
        uint32_t ha[2][4];
        #pragma unroll
        for (int mf = 0; mf < 2; mf++) {
            float h00 = 0.5f * ga[mf][0][0] * (1.f + tanha(0.5f * ga[mf][0][0])) * va[mf][0][0];
            float h01 = 0.5f * ga[mf][0][1] * (1.f + tanha(0.5f * ga[mf][0][1])) * va[mf][0][1];
            float h02 = 0.5f * ga[mf][0][2] * (1.f + tanha(0.5f * ga[mf][0][2])) * va[mf][0][2];
            float h03 = 0.5f * ga[mf][0][3] * (1.f + tanha(0.5f * ga[mf][0][3])) * va[mf][0][3];
            float h10 = 0.5f * ga[mf][1][0] * (1.f + tanha(0.5f * ga[mf][1][0])) * va[mf][1][0];
            float h11 = 0.5f * ga[mf][1][1] * (1.f + tanha(0.5f * ga[mf][1][1])) * va[mf][1][1];
            float h12 = 0.5f * ga[mf][1][2] * (1.f + tanha(0.5f * ga[mf][1][2])) * va[mf][1][2];
            float h13 = 0.5f * ga[mf][1][3] * (1.f + tanha(0.5f * ga[mf][1][3])) * va[mf][1][3];
            ha[mf][0] = pack2(h00, h01);
            ha[mf][1] = pack2(h02, h03);
            ha[mf][2] = pack2(h10, h11);
            ha[mf][3] = pack2(h12, h13);
        }
        #pragma unroll
        for (int dt = 0; dt < 8; dt++) {
            const int c = ((dt * 8) ^ q8) + r;
            uint32_t fb0 = f0[c], fb1 = f1[c];
            mma_f16(oacc[0][dt], ha[0], fb0, fb1);
            mma_f16(oacc[1][dt], ha[1], fb0, fb1);
        }
    }

    #pragma unroll
    for (int mf = 0; mf < 2; mf++) {
        const int gr0 = row0 + m0 + mf * 16 + r;
        const float* x0 = x + ((size_t)b * NN + gr0) * DD;
        const float* x1 = x0 + 8 * DD;
        float* o0 = out + ((size_t)b * NN + gr0) * DD;
        float* o1 = o0 + 8 * DD;
        #pragma unroll
        for (int dt = 0; dt < 8; dt++) {
            const int cc = dt * 8 + 2 * q;
            float2 r0v = *(const float2*)(x0 + cc);
            float2 r1v = *(const float2*)(x1 + cc);
            *(float2*)(o0 + cc) = make_float2(oacc[mf][dt][0] + r0v.x, oacc[mf][dt][1] + r0v.y);
            *(float2*)(o1 + cc) = make_float2(oacc[mf][dt][2] + r1v.x, oacc[mf][dt][3] + r1v.y);
        }
    }
}

// ======================= launch =======================
extern "C" void kernel_launch(void* const* d_in, const int* in_sizes, int n_in,
                              void* d_out, int out_size) {
    const float* x     = (const float*)d_in[0];
    const float* s     = (const float*)d_in[1];
    const float* W     = (const float*)d_in[2];
    const float* bias  = (const float*)d_in[3];
    const float* scale = (const float*)d_in[4];
    float* out = (float*)d_out;

    k1_reset<<<1, 1>>>();

    cudaFuncSetAttribute(k1_mma, cudaFuncAttributeMaxDynamicSharedMemorySize, K1_SMEM);
    k1_mma<<<dim3(444), 256, K1_SMEM>>>(s, W, bias);

    k2_normalize<<<dim3(64, 4), 256>>>();

    cudaFuncSetAttribute(k3_main, cudaFuncAttributeMaxDynamicSharedMemorySize, K3_SMEM);
    k3_main<<<dim3(1024), 256, K3_SMEM>>>(x, scale, out);
}

// round 13
// speedup vs baseline: 1.0559x; 1.0559x over previous
#include <cuda_runtime.h>
#include <cuda_fp16.h>
#include <cstdint>
#include <math.h>

#define BB   64
#define NN   4096
#define DD   64
#define HH   256
#define SS   1024
#define TOT  49152   // 3 * D * H
#define WPB  24576   // half2 words per batch (3*D*H/2)

// raw hypernet output (k1 -> k2)
__device__ float g_params[BB * (size_t)TOT];
// normalized fp16 weights, half2-packed along k, XOR-swizzled (k2 -> k3)
__device__ uint32_t g_wT[BB * (size_t)WPB];

// ======================= helpers =======================
__device__ __forceinline__ float tanha(float x) {
    float y;
    asm("tanh.approx.f32 %0, %1;" : "=f"(y) : "f"(x));
    return y;
}
__device__ __forceinline__ uint32_t pack2(float lo, float hi) {
    __half2 h = __floats2half2_rn(lo, hi);
    return *(uint32_t*)&h;
}
__device__ __forceinline__ uint32_t smem_u32(const void* p) {
    uint32_t a;
    asm("{ .reg .u64 t; cvta.to.shared.u64 t, %1; cvt.u32.u64 %0, t; }" : "=r"(a) : "l"(p));
    return a;
}
__device__ __forceinline__ void cpa16(uint32_t dst, const void* src) {
    asm volatile("cp.async.cg.shared.global [%0], [%1], 16;" :: "r"(dst), "l"(src));
}
#define CP_COMMIT() asm volatile("cp.async.commit_group;" ::: "memory")
#define CP_WAIT0()  asm volatile("cp.async.wait_group 0;" ::: "memory")
#define CP_WAIT1()  asm volatile("cp.async.wait_group 1;" ::: "memory")

// D += A * B  (m16n8k8, tf32 inputs, fp32 accum) — kernel 1
__device__ __forceinline__ void mma_tf32(float* d, const uint32_t* a, uint32_t b0, uint32_t b1) {
    asm volatile("mma.sync.aligned.m16n8k8.row.col.f32.tf32.tf32.f32 "
                 "{%0,%1,%2,%3}, {%4,%5,%6,%7}, {%8,%9}, {%0,%1,%2,%3};"
                 : "+f"(d[0]), "+f"(d[1]), "+f"(d[2]), "+f"(d[3])
                 : "r"(a[0]), "r"(a[1]), "r"(a[2]), "r"(a[3]), "r"(b0), "r"(b1));
}
// D += A * B  (m16n8k16, fp16 inputs, fp32 accum) — kernel 3
__device__ __forceinline__ void mma_f16(float* d, const uint32_t* a, uint32_t b0, uint32_t b1) {
    asm volatile("mma.sync.aligned.m16n8k16.row.col.f32.f16.f16.f32 "
                 "{%0,%1,%2,%3}, {%4,%5,%6,%7}, {%8,%9}, {%0,%1,%2,%3};"
                 : "+f"(d[0]), "+f"(d[1]), "+f"(d[2]), "+f"(d[3])
                 : "r"(a[0]), "r"(a[1]), "r"(a[2]), "r"(a[3]), "r"(b0), "r"(b1));
}

// ======================= kernel 1: hypernet GEMM via mma.sync tf32 (reverted R11, 57.8us) =======================
#define K1_SMEM ((2 * 64 * 36 + 2 * 32 * 136) * 4)   // 53248 B

__global__ __launch_bounds__(256) void k1_mma(const float* __restrict__ s,
                                              const float* __restrict__ W,
                                              const float* __restrict__ bias) {
    extern __shared__ float sk[];
    float* sA = sk;              // 2 * 2304
    float* sB = sk + 4608;       // 2 * 4352
    const int n0  = blockIdx.x * 128;
    const int tid = threadIdx.x;
    const int w = tid >> 5, lane = tid & 31;
    const int r = lane >> 2, q = lane & 3;
    const int m0 = (w & 1) * 32, nw = (w >> 1) * 32;
    const uint32_t sbA = smem_u32(sA), sbB = smem_u32(sB);

    #define K1_LOAD(st, k0) do {                                                   \
        _Pragma("unroll")                                                          \
        for (int i = 0; i < 2; i++) {                                              \
            int c = tid + i * 256;                                                 \
            int row = c >> 3, cc = c & 7;                                          \
            cpa16(sbA + (uint32_t)((st) * 2304 + row * 36 + cc * 4) * 4,           \
                  s + (size_t)row * SS + (k0) + cc * 4);                           \
        }                                                                          \
        _Pragma("unroll")                                                          \
        for (int i = 0; i < 4; i++) {                                              \
            int c = tid + i * 256;                                                 \
            int row = c >> 5, cc = c & 31;                                         \
            cpa16(sbB + (uint32_t)((st) * 4352 + row * 136 + cc * 4) * 4,          \
                  W + (size_t)((k0) + row) * TOT + n0 + cc * 4);                   \
        }                                                                          \
    } while (0)

    float acc[2][4][4];
    #pragma unroll
    for (int mf = 0; mf < 2; mf++)
        #pragma unroll
        for (int nf = 0; nf < 4; nf++)
            acc[mf][nf][0] = acc[mf][nf][1] = acc[mf][nf][2] = acc[mf][nf][3] = 0.f;

    K1_LOAD(0, 0);  CP_COMMIT();
    K1_LOAD(1, 32); CP_COMMIT();

    for (int ks = 0; ks < 32; ks++) {
        CP_WAIT1();
        __syncthreads();
        const int st = ks & 1;
        const float* A  = sA + st * 2304;
        const float* Bp = sB + st * 4352;
        #pragma unroll
        for (int kk = 0; kk < 4; kk++) {
            uint32_t a[2][4];
            #pragma unroll
            for (int mf = 0; mf < 2; mf++) {
                const int mr = m0 + mf * 16 + r;
                a[mf][0] = __float_as_uint(A[mr * 36 + kk * 8 + q]);
                a[mf][1] = __float_as_uint(A[(mr + 8) * 36 + kk * 8 + q]);
                a[mf][2] = __float_as_uint(A[mr * 36 + kk * 8 + q + 4]);
                a[mf][3] = __float_as_uint(A[(mr + 8) * 36 + kk * 8 + q + 4]);
            }
            #pragma unroll
            for (int nf = 0; nf < 4; nf++) {
                const int cb = nw + nf * 8 + r;
                uint32_t b0 = __float_as_uint(Bp[(kk * 8 + q) * 136 + cb]);
                uint32_t b1 = __float_as_uint(Bp[(kk * 8 + q + 4) * 136 + cb]);
                mma_tf32(acc[0][nf], a[0], b0, b1);
                mma_tf32(acc[1][nf], a[1], b0, b1);
            }
        }
        __syncthreads();
        const int kn = (ks + 2) * 32;
        if (kn < SS) { K1_LOAD(st, kn); }
        CP_COMMIT();
    }

    #pragma unroll
    for (int nf = 0; nf < 4; nf++) {
        float2 bv = *(const float2*)(bias + n0 + nw + nf * 8 + 2 * q);
        #pragma unroll
        for (int mf = 0; mf < 2; mf++) {
            const int mr = m0 + mf * 16 + r;
            float* o0 = g_params + (size_t)mr * TOT + n0 + nw + nf * 8 + 2 * q;
            *(float2*)o0 = make_float2(acc[mf][nf][0] + bv.x, acc[mf][nf][1] + bv.y);
            float* o1 = g_params + (size_t)(mr + 8) * TOT + n0 + nw + nf * 8 + 2 * q;
            *(float2*)o1 = make_float2(acc[mf][nf][2] + bv.x, acc[mf][nf][3] + bv.y);
        }
    }
    #undef K1_LOAD
}

// ======================= kernel 2: normalize -> fp16 swizzled, grid (64, 4) =======================
__global__ __launch_bounds__(256) void k2_normalize() {
    __shared__ float red[256];
    __shared__ float sinv[64];
    const int b = blockIdx.x, quad = blockIdx.y, tid = threadIdx.x;
    const float* P = g_params + (size_t)b * TOT;
    uint32_t* dst = g_wT + (size_t)b * WPB;

    #pragma unroll
    for (int m = 0; m < 2; m++) {
        const float* src = P + m * 16384;
        const int hl = tid & 63, part = tid >> 6;
        const int h = quad * 64 + hl;
        {
            float ss = 0.f;
            #pragma unroll 4
            for (int d = part * 16; d < part * 16 + 16; d++) {
                float v = src[d * 256 + h];
                ss += v * v;
            }
            red[tid] = ss;
        }
        __syncthreads();
        if (tid < 64)
            sinv[tid] = 1.f / fmaxf(sqrtf(red[tid] + red[tid + 64] + red[tid + 128] + red[tid + 192]), 1e-12f);
        __syncthreads();
        #pragma unroll
        for (int i = 0; i < 8; i++) {
            int idx = tid + i * 256;
            int kp = idx >> 6, hl2 = idx & 63;
            int h2 = quad * 64 + hl2;
            float inv = sinv[hl2];
            float a = src[(2 * kp) * 256 + h2] * inv;
            float c = src[(2 * kp + 1) * 256 + h2] * inv;
            dst[m * 8192 + kp * 256 + (h2 ^ ((kp & 3) << 3))] = pack2(a, c);
        }
        __syncthreads();
    }
    {
        const float* src = P + 32768;
        const int dl = tid & 15, part = tid >> 4;
        const int d = quad * 16 + dl;
        {
            float ss = 0.f;
            #pragma unroll 4
            for (int h = part * 16; h < part * 16 + 16; h++) {
                float v = src[h * 64 + d];
                ss += v * v;
            }
            red[tid] = ss;
        }
        __syncthreads();
        if (tid < 16) {
            float t = 0.f;
            #pragma unroll
            for (int p = 0; p < 16; p++) t += red[p * 16 + tid];
            sinv[tid] = 1.f / fmaxf(sqrtf(t), 1e-12f);
        }
        __syncthreads();
        #pragma unroll
        for (int i = 0; i < 8; i++) {
            int idx = tid + i * 256;
            int hp = idx >> 4, dl2 = idx & 15;
            int d2 = quad * 16 + dl2;
            float inv = sinv[dl2];
            float a = src[(2 * hp) * 64 + d2] * inv;
            float c = src[(2 * hp + 1) * 64 + d2] * inv;
            dst[16384 + hp * 64 + (d2 ^ ((hp & 3) << 3))] = pack2(a, c);
        }
    }
}

// ======================= kernel 3: fp16 mma, software-pipelined chunks =======================
#define K3_XN_OFF 24640
#define K3_SMEM   ((24576 + 64 + 9216) * 4)   // 135424 B

__global__ __launch_bounds__(256, 1) void k3_main(const float* __restrict__ x,
                                                  const float* __restrict__ scale,
                                                  float* __restrict__ out) {
    extern __shared__ uint32_t su[];
    float* ssc = (float*)(su + 24576);       // scale [64]
    uint32_t* xnw = su + K3_XN_OFF;          // [256][36] half2 words
    const int tid = threadIdx.x, w = tid >> 5, lane = tid & 31;
    const int b = blockIdx.x >> 4;
    const int row0 = (blockIdx.x & 15) * 256;
    const int m0 = w * 32;
    const int r = lane >> 2, q = lane & 3, q8 = q << 3;
    const uint32_t sb = smem_u32(su);

    {
        const uint32_t* wsrc = g_wT + (size_t)b * WPB;
        #pragma unroll 6
        for (int i = tid; i < 6144; i += 256)
            cpa16(sb + (uint32_t)i * 16, wsrc + i * 4);
        CP_COMMIT();
    }
    if (tid < 64) ssc[tid] = scale[tid];
    __syncthreads();

    // ---- stage RMSNorm'd xn: one thread per row ----
    {
        const float4* xr = (const float4*)(x + ((size_t)b * NN + row0 + tid) * DD);
        float4 v[16];
        float ssq = 0.f;
        #pragma unroll
        for (int i = 0; i < 16; i++) {
            v[i] = xr[i];
            ssq += v[i].x * v[i].x + v[i].y * v[i].y + v[i].z * v[i].z + v[i].w * v[i].w;
        }
        const float rr = rsqrtf(ssq * (1.0f / 64.0f) + 1e-6f);
        uint32_t* xd = xnw + tid * 36;
        #pragma unroll
        for (int i = 0; i < 8; i++) {
            float4 a = v[2 * i], c = v[2 * i + 1];
            float4 sA = *(const float4*)&ssc[8 * i];
            float4 sB = *(const float4*)&ssc[8 * i + 4];
            uint4 o;
            o.x = pack2(a.x * rr * sA.x, a.y * rr * sA.y);
            o.y = pack2(a.z * rr * sA.z, a.w * rr * sA.w);
            o.z = pack2(c.x * rr * sB.x, c.y * rr * sB.y);
            o.w = pack2(c.z * rr * sB.z, c.w * rr * sB.w);
            *(uint4*)&xd[4 * i] = o;
        }
    }
    CP_WAIT0();
    __syncthreads();

    const uint32_t* Wg = su;
    const uint32_t* Wv = su + 8192;
    const uint32_t* Wf = su + 16384;

    // ---- cache A fragments: 4 k16 tiles x 2 m-frags (32 regs) ----
    uint32_t xa[4][2][4];
    #pragma unroll
    for (int kt = 0; kt < 4; kt++) {
        #pragma unroll
        for (int mf = 0; mf < 2; mf++) {
            const uint32_t* xb = xnw + (m0 + mf * 16 + r) * 36 + kt * 8 + q;
            xa[kt][mf][0] = xb[0];
            xa[kt][mf][1] = xb[8 * 36];
            xa[kt][mf][2] = xb[4];
            xa[kt][mf][3] = xb[8 * 36 + 4];
        }
    }

    float oacc[2][8][4];
    #pragma unroll
    for (int mf = 0; mf < 2; mf++)
        #pragma unroll
        for (int i = 0; i < 8; i++)
            oacc[mf][i][0] = oacc[mf][i][1] = oacc[mf][i][2] = oacc[mf][i][3] = 0.f;

    // ---- MMA1 for one 16-col chunk into ga/va ----
    #define MMA1_CHUNK(ch, ga, va) do {                                             \
        const int _nc = (ch) * 16;                                                  \
        _Pragma("unroll")                                                           \
        for (int _mf = 0; _mf < 2; _mf++)                                           \
            _Pragma("unroll")                                                       \
            for (int _nt = 0; _nt < 2; _nt++) {                                     \
                (ga)[_mf][_nt][0] = (ga)[_mf][_nt][1] = (ga)[_mf][_nt][2] = (ga)[_mf][_nt][3] = 0.f; \
                (va)[_mf][_nt][0] = (va)[_mf][_nt][1] = (va)[_mf][_nt][2] = (va)[_mf][_nt][3] = 0.f; \
            }                                                                       \
        const int _c0 = (_nc ^ q8) + r;                                             \
        const int _c1 = ((_nc + 8) ^ q8) + r;                                       \
        _Pragma("unroll")                                                           \
        for (int _kt = 0; _kt < 4; _kt++) {                                         \
            const uint32_t* _g0 = Wg + (_kt * 8 + q) * 256;                         \
            const uint32_t* _g1 = Wg + (_kt * 8 + q + 4) * 256;                     \
            const uint32_t* _v0 = Wv + (_kt * 8 + q) * 256;                         \
            const uint32_t* _v1 = Wv + (_kt * 8 + q + 4) * 256;                     \
            uint32_t _gb00 = _g0[_c0], _gb10 = _g1[_c0], _gb01 = _g0[_c1], _gb11 = _g1[_c1]; \
            uint32_t _vb00 = _v0[_c0], _vb10 = _v1[_c0], _vb01 = _v0[_c1], _vb11 = _v1[_c1]; \
            _Pragma("unroll")                                                       \
            for (int _mf = 0; _mf < 2; _mf++) {                                     \
                mma_f16((ga)[_mf][0], xa[_kt][_mf], _gb00, _gb10);                  \
                mma_f16((ga)[_mf][1], xa[_kt][_mf], _gb01, _gb11);                  \
                mma_f16((va)[_mf][0], xa[_kt][_mf], _vb00, _vb10);                  \
                mma_f16((va)[_mf][1], xa[_kt][_mf], _vb01, _vb11);                  \
            }                                                                       \
        }                                                                           \
    } while (0)

    // ---- silu + MMA2 accumulate for one chunk ----
    #define SILU_MMA2(ch, ga, va) do {                                              \
        const int _hp0 = (ch) * 8;                                                  \
        const uint32_t* _f0 = Wf + (_hp0 + q) * 64;                                 \
        const uint32_t* _f1 = Wf + (_hp0 + q + 4) * 64;                             \
        uint32_t _ha[2][4];                                                         \
        _Pragma("unroll")                                                           \
        for (int _mf = 0; _mf < 2; _mf++) {                                         \
            float _h00 = 0.5f * (ga)[_mf][0][0] * (1.f + tanha(0.5f * (ga)[_mf][0][0])) * (va)[_mf][0][0]; \
            float _h01 = 0.5f * (ga)[_mf][0][1] * (1.f + tanha(0.5f * (ga)[_mf][0][1])) * (va)[_mf][0][1]; \
            float _h02 = 0.5f * (ga)[_mf][0][2] * (1.f + tanha(0.5f * (ga)[_mf][0][2])) * (va)[_mf][0][2]; \
            float _h03 = 0.5f * (ga)[_mf][0][3] * (1.f + tanha(0.5f * (ga)[_mf][0][3])) * (va)[_mf][0][3]; \
            float _h10 = 0.5f * (ga)[_mf][1][0] * (1.f + tanha(0.5f * (ga)[_mf][1][0])) * (va)[_mf][1][0]; \
            float _h11 = 0.5f * (ga)[_mf][1][1] * (1.f + tanha(0.5f * (ga)[_mf][1][1])) * (va)[_mf][1][1]; \
            float _h12 = 0.5f * (ga)[_mf][1][2] * (1.f + tanha(0.5f * (ga)[_mf][1][2])) * (va)[_mf][1][2]; \
            float _h13 = 0.5f * (ga)[_mf][1][3] * (1.f + tanha(0.5f * (ga)[_mf][1][3])) * (va)[_mf][1][3]; \
            _ha[_mf][0] = pack2(_h00, _h01);                                        \
            _ha[_mf][1] = pack2(_h02, _h03);                                        \
            _ha[_mf][2] = pack2(_h10, _h11);                                        \
            _ha[_mf][3] = pack2(_h12, _h13);                                        \
        }                                                                           \
        _Pragma("unroll")                                                           \
        for (int _dt = 0; _dt < 8; _dt++) {                                         \
            const int _c = ((_dt * 8) ^ q8) + r;                                    \
            uint32_t _fb0 = _f0[_c], _fb1 = _f1[_c];                                \
            mma_f16(oacc[0][_dt], _ha[0], _fb0, _fb1);                              \
            mma_f16(oacc[1][_dt], _ha[1], _fb0, _fb1);                              \
        }                                                                           \
    } while (0)

    // ---- software-pipelined chunk loop: MMA1(ch+1) overlaps silu/MMA2(ch) ----
    float gaA[2][2][4], vaA[2][2][4], gaB[2][2][4], vaB[2][2][4];
    MMA1_CHUNK(0, gaA, vaA);
    #pragma unroll 2
    for (int cp = 0; cp < 7; cp++) {
        const int ch = cp * 2;
        MMA1_CHUNK(ch + 1, gaB, vaB);
        SILU_MMA2(ch, gaA, vaA);
        MMA1_CHUNK(ch + 2, gaA, vaA);
        SILU_MMA2(ch + 1, gaB, vaB);
    }
    MMA1_CHUNK(15, gaB, vaB);
    SILU_MMA2(14, gaA, vaA);
    SILU_MMA2(15, gaB, vaB);

    #undef MMA1_CHUNK
    #undef SILU_MMA2

    // ---- epilogue: residual + store; warp owns out[32 x 64] ----
    #pragma unroll
    for (int mf = 0; mf < 2; mf++) {
        const int gr0 = row0 + m0 + mf * 16 + r;
        const float* x0 = x + ((size_t)b * NN + gr0) * DD;
        const float* x1 = x0 + 8 * DD;
        float* o0 = out + ((size_t)b * NN + gr0) * DD;
        float* o1 = o0 + 8 * DD;
        #pragma unroll
        for (int dt = 0; dt < 8; dt++) {
            const int cc = dt * 8 + 2 * q;
            float2 r0v = *(const float2*)(x0 + cc);
            float2 r1v = *(const float2*)(x1 + cc);
            *(float2*)(o0 + cc) = make_float2(oacc[mf][dt][0] + r0v.x, oacc[mf][dt][1] + r0v.y);
            *(float2*)(o1 + cc) = make_float2(oacc[mf][dt][2] + r1v.x, oacc[mf][dt][3] + r1v.y);
        }
    }
}

// ======================= launch =======================
extern "C" void kernel_launch(void* const* d_in, const int* in_sizes, int n_in,
                              void* d_out, int out_size) {
    const float* x     = (const float*)d_in[0];
    const float* s     = (const float*)d_in[1];
    const float* W     = (const float*)d_in[2];
    const float* bias  = (const float*)d_in[3];
    const float* scale = (const float*)d_in[4];
    float* out = (float*)d_out;

    cudaFuncSetAttribute(k1_mma, cudaFuncAttributeMaxDynamicSharedMemorySize, K1_SMEM);
    k1_mma<<<dim3(TOT / 128), 256, K1_SMEM>>>(s, W, bias);

    k2_normalize<<<dim3(64, 4), 256>>>();

    cudaFuncSetAttribute(k3_main, cudaFuncAttributeMaxDynamicSharedMemorySize, K3_SMEM);
    k3_main<<<dim3(1024), 256, K3_SMEM>>>(x, scale, out);
}